// round 11
// baseline (speedup 1.0000x reference)
#include <cuda_runtime.h>
#include <cuda_fp16.h>
#include <math.h>

#define NN      20000
#define NNP     20480        // padded for csr_scan vector path
#define NE      500000
#define NGR     64
#define NGAUSS  100
#define NLAYER  6
#define FCW     128
#define EMBW    92

#define DELTA     (6.0f/99.0f)
#define INV_DELTA (99.0f/6.0f)
#define COEFF     (-0.5f/(DELTA*DELTA))

// nearest-neighbor distance table: h = DELTA/256
#define MT2       25346
#define T2_INVH   4224.0f    // 99*256/6
#define T2_H      (1.0f/4224.0f)

// BN statistics subsampling
#define SUB       8
#define NSAMP     (NE/SUB)   // 62500

#define TAB_BLOCKS 148
#define GEMM_SMEM  ((64*256 + 32*64)*4)
#define TAB_SMEM   ((NGAUSS*128 + 128 + 48)*4)

#define BIGGRID    1184

// ---------------- scratch (device globals; no allocs allowed) ----------------
__device__ float  g_x[NN*64];
__device__ __half g_Ph[NN*128];           // P = x@W1, permuted, fp16
__device__ __half g_Qh[NN*128];           // Q = x@W2, permuted, fp16
__device__ __half g_Th6[NLAYER*MT2*128];  // all 6 layers' ef@W3+b tables, permuted fp16
__device__ int    g_deg[NNP];
__device__ int    g_rowstart[NNP+1];
__device__ int    g_cursor[NNP];
__device__ unsigned int g_pack[NE];       // src (15b) | m (<<15), CSR order
__device__ double g_bn_sum[NLAYER*128];
__device__ double g_bn_ssq[NLAYER*128];
__device__ float  g_mol[NGR*64];
__device__ float  g_cnt[NGR];

// ---------------- helpers ----------------
__device__ __forceinline__ float splusf(float x){
    float e = __expf(-fabsf(x));
    return fmaxf(x, 0.0f) + __logf(1.0f + e);
}
__device__ __forceinline__ float tanhx(float x){
    float y; asm("tanh.approx.f32 %0, %1;" : "=f"(y) : "f"(x)); return y;
}
__device__ __forceinline__ float sigmt(float x){   // sigmoid via 1 MUFU
    return fmaf(0.5f, tanhx(0.5f*x), 0.5f);
}
// channel c (0..127) -> permuted position: lane L holds {2L,2L+1,2L+64,2L+65}
__device__ __forceinline__ int chpos(int c){
    return ((c & 63) >> 1)*4 + ((c >> 6) << 1) + (c & 1);
}
__device__ __forceinline__ void ld_h4(const __half* p, float& a, float& b, float& c, float& d){
    uint2 u = *reinterpret_cast<const uint2*>(p);
    float2 f0 = __half22float2(*reinterpret_cast<__half2*>(&u.x));
    float2 f1 = __half22float2(*reinterpret_cast<__half2*>(&u.y));
    a = f0.x; b = f0.y; c = f1.x; d = f1.y;
}
// add two loaded uint2s (half2 pairs), return 4 floats
__device__ __forceinline__ void qt_sum4(uint2 uq, uint2 ut,
                                        float& a, float& b, float& c, float& d){
    __half2 s01 = __hadd2(*reinterpret_cast<__half2*>(&uq.x), *reinterpret_cast<__half2*>(&ut.x));
    __half2 s23 = __hadd2(*reinterpret_cast<__half2*>(&uq.y), *reinterpret_cast<__half2*>(&ut.y));
    float2 f0 = __half22float2(s01);
    float2 f1 = __half22float2(s23);
    a = f0.x; b = f0.y; c = f1.x; d = f1.y;
}

// ---------------- x = embedding[an] @ nuc_W + nuc_b ----------------
__global__ void nuc_kernel(const int* __restrict__ an, const float* __restrict__ emb,
                           const float* __restrict__ W, const float* __restrict__ b){
    __shared__ float Ws[EMBW*64];
    __shared__ float bs[64];
    for (int i = threadIdx.x; i < EMBW*64; i += blockDim.x) Ws[i] = W[i];
    if (threadIdx.x < 64) bs[threadIdx.x] = b[threadIdx.x];
    __syncthreads();
    int lane = threadIdx.x & 31;
    int warp = (blockIdx.x*blockDim.x + threadIdx.x) >> 5;
    int nw   = (gridDim.x*blockDim.x) >> 5;
    for (int n = warp; n < NN; n += nw){
        const float* er = emb + an[n]*EMBW;
        float a0 = bs[lane], a1 = bs[lane+32];
        #pragma unroll 4
        for (int e = 0; e < EMBW; e++){
            float v = __ldg(er + e);
            a0 = fmaf(v, Ws[e*64 + lane],      a0);
            a1 = fmaf(v, Ws[e*64 + lane + 32], a1);
        }
        g_x[n*64 + lane]      = a0;
        g_x[n*64 + lane + 32] = a1;
    }
}

// ---------------- one-time zeroing ----------------
__global__ void csr_zero(){
    int i = blockIdx.x*blockDim.x + threadIdx.x;
    if (i < NNP) g_deg[i] = 0;
    if (i < NGR*64) g_mol[i] = 0.0f;
    if (i < NGR)    g_cnt[i] = 0.0f;
    if (i < NLAYER*128){ g_bn_sum[i] = 0.0; g_bn_ssq[i] = 0.0; }
}
__global__ void csr_hist(const int* __restrict__ nbr){
    int i = blockIdx.x*blockDim.x + threadIdx.x;
    int stride = gridDim.x*blockDim.x;
    for (int e = i; e < NE; e += stride)
        atomicAdd(&g_deg[__ldg(nbr + NE + e)], 1);
}
__global__ void csr_scan(){   // single block, 1024 threads, 20 items each (padded)
    __shared__ int wsum[32];
    int t = threadIdx.x, lane = t & 31, wid = t >> 5;
    int base = t*20;
    int4 v[5];
    int loc = 0;
    #pragma unroll
    for (int j = 0; j < 5; j++){
        v[j] = *reinterpret_cast<const int4*>(g_deg + base + j*4);
        loc += v[j].x + v[j].y + v[j].z + v[j].w;
    }
    int sc = loc;
    #pragma unroll
    for (int off = 1; off < 32; off <<= 1){
        int u = __shfl_up_sync(0xffffffffu, sc, off);
        if (lane >= off) sc += u;
    }
    if (lane == 31) wsum[wid] = sc;
    __syncthreads();
    if (wid == 0){
        int w = wsum[lane];
        #pragma unroll
        for (int off = 1; off < 32; off <<= 1){
            int u = __shfl_up_sync(0xffffffffu, w, off);
            if (lane >= off) w += u;
        }
        wsum[lane] = w;
    }
    __syncthreads();
    int run = sc - loc + (wid ? wsum[wid-1] : 0);
    #pragma unroll
    for (int j = 0; j < 5; j++){
        int4 rs;
        rs.x = run; run += v[j].x;
        rs.y = run; run += v[j].y;
        rs.z = run; run += v[j].z;
        rs.w = run; run += v[j].w;
        *reinterpret_cast<int4*>(g_rowstart + base + j*4) = rs;
        *reinterpret_cast<int4*>(g_cursor   + base + j*4) = rs;
    }
    if (t == 1023) g_rowstart[NNP] = wsum[31];
}
__global__ void csr_scatter(const int* __restrict__ nbr, const float* __restrict__ dist){
    int i = blockIdx.x*blockDim.x + threadIdx.x;
    int stride = gridDim.x*blockDim.x;
    for (int e = i; e < NE; e += stride){
        int dn = __ldg(nbr + NE + e);
        int sn = __ldg(nbr + e);
        float d = __ldg(dist + e);
        int m = min(__float2int_rn(d * T2_INVH), MT2 - 1);
        int pos = atomicAdd(&g_cursor[dn], 1);
        g_pack[pos] = (unsigned)sn | ((unsigned)m << 15);
    }
}

// ---- build ALL 6 tables up front: T6[l][m] = ef(m*h)@W3_l + conv_b_l (fp16, permuted) ----
__global__ void build_tables(const float* __restrict__ convW, const float* __restrict__ convb){
    extern __shared__ float sm[];
    float* W3s = sm;                 // [100][128]
    float* bs  = sm + NGAUSS*128;    // [128]
    float* wsm = bs + 128;           // [2][24]
    int layer = blockIdx.x / TAB_BLOCKS;
    int tb    = blockIdx.x % TAB_BLOCKS;
    const float* W3 = convW + layer*228*128 + 128*128;
    const float* bl = convb + layer*128;
    __half* Tl = g_Th6 + (size_t)layer*MT2*128;
    for (int i = threadIdx.x; i < NGAUSS*128; i += blockDim.x) W3s[i] = W3[i];
    if (threadIdx.x < 128) bs[threadIdx.x] = bl[threadIdx.x];
    __syncthreads();
    int half = threadIdx.x >> 7;      // 0/1: two m-rows per iteration
    int j    = threadIdx.x & 127;
    int pj   = chpos(j);
    int per = (MT2 + TAB_BLOCKS - 1) / TAB_BLOCKS;
    int m0 = tb*per;
    int m1 = min(m0 + per, MT2);
    for (int mb = m0; mb < m1; mb += 2){
        int m = mb + half;
        bool valid = (m < m1);
        float d = (float)m * T2_H;
        int kc = __float2int_rn(d * INV_DELTA);
        int k0 = max(kc - 8, 0);
        int k1 = min(kc + 8, NGAUSS - 1);
        int cnt = k1 - k0 + 1;
        if (valid && j < cnt){
            float t = d - (float)(k0+j)*DELTA;
            wsm[half*24 + j] = __expf(COEFF*t*t);
        }
        __syncthreads();
        if (valid){
            float acc = bs[j];
            for (int k = 0; k < cnt; k++)
                acc = fmaf(wsm[half*24 + k], W3s[(k0+k)*128 + j], acc);
            Tl[m*128 + pj] = __float2half_rn(acc);
        }
        __syncthreads();
    }
}

// ---------------- P = x@W1, Q = x@W2 (fp16, permuted) ----------------
__global__ void gemm_ab(const float* __restrict__ Wl){
    extern __shared__ float sm[];
    float* Wc = sm;             // [64][256]
    float* xt = sm + 64*256;    // [32][64]
    for (int i = threadIdx.x; i < 64*256; i += blockDim.x){
        int f = i >> 8, j = i & 255;
        Wc[i] = (j < 128) ? Wl[f*128 + j] : Wl[(64+f)*128 + (j-128)];
    }
    int n0 = blockIdx.x * 32;   // 625 * 32 == 20000
    for (int i = threadIdx.x; i < 32*64; i += blockDim.x)
        xt[i] = g_x[(n0 + (i>>6))*64 + (i&63)];
    __syncthreads();
    int j = threadIdx.x;
    float acc[32];
    #pragma unroll
    for (int t = 0; t < 32; t++) acc[t] = 0.0f;
    for (int f = 0; f < 64; f += 4){
        float w0 = Wc[f*256 + j], w1 = Wc[(f+1)*256 + j];
        float w2 = Wc[(f+2)*256 + j], w3 = Wc[(f+3)*256 + j];
        #pragma unroll
        for (int t = 0; t < 32; t++){
            float4 xv = *reinterpret_cast<const float4*>(xt + t*64 + f);
            acc[t] = fmaf(xv.x, w0, fmaf(xv.y, w1, fmaf(xv.z, w2, fmaf(xv.w, w3, acc[t]))));
        }
    }
    int cp = chpos(j & 127);
    if (j < 128){
        #pragma unroll
        for (int t = 0; t < 32; t++)
            g_Ph[(n0+t)*128 + cp] = __float2half_rn(acc[t]);
    } else {
        #pragma unroll
        for (int t = 0; t < 32; t++)
            g_Qh[(n0+t)*128 + cp] = __float2half_rn(acc[t]);
    }
}

// ---- BN stats over every SUB-th edge, edge-centric flat loop, unroll 2 ----
__global__ void bn_pass(const int* __restrict__ nbr, const float* __restrict__ dist, int layer){
    __shared__ float s_sum[128];
    __shared__ float s_ssq[128];
    if (threadIdx.x < 128){ s_sum[threadIdx.x] = 0.0f; s_ssq[threadIdx.x] = 0.0f; }
    __syncthreads();
    const __half* Tl = g_Th6 + (size_t)layer*MT2*128;
    int lane = threadIdx.x & 31;
    int warp = (blockIdx.x*blockDim.x + threadIdx.x) >> 5;
    int nw   = (gridDim.x*blockDim.x) >> 5;
    float s0=0,s1=0,s2=0,s3=0, q0=0,q1=0,q2=0,q3=0;
    for (int s = warp; s < NSAMP; s += 2*nw){
        int s2i = s + nw;
        bool has2 = (s2i < NSAMP);
        int e  = s * SUB;
        int e2 = s2i * SUB;
        int dn  = __ldg(nbr + NE + e);
        int sn  = __ldg(nbr + e);
        float d = __ldg(dist + e);
        int dn2 = 0, sn2 = 0; float d2 = 0.0f;
        if (has2){ dn2 = __ldg(nbr + NE + e2); sn2 = __ldg(nbr + e2); d2 = __ldg(dist + e2); }
        int m  = min(__float2int_rn(d  * T2_INVH), MT2 - 1);
        int m2 = min(__float2int_rn(d2 * T2_INVH), MT2 - 1);
        uint2 up  = *reinterpret_cast<const uint2*>(g_Ph + dn*128 + lane*4);
        uint2 uq  = *reinterpret_cast<const uint2*>(g_Qh + sn*128 + lane*4);
        uint2 ut  = *reinterpret_cast<const uint2*>(Tl + (size_t)m*128 + lane*4);
        uint2 up2 = make_uint2(0,0), uq2 = make_uint2(0,0), ut2 = make_uint2(0,0);
        if (has2){
            up2 = *reinterpret_cast<const uint2*>(g_Ph + dn2*128 + lane*4);
            uq2 = *reinterpret_cast<const uint2*>(g_Qh + sn2*128 + lane*4);
            ut2 = *reinterpret_cast<const uint2*>(Tl + (size_t)m2*128 + lane*4);
        }
        {
            float p0,p1,p2,p3, a0,a1,a2,a3;
            qt_sum4(uq, ut, a0,a1,a2,a3);
            float2 f0 = __half22float2(*reinterpret_cast<__half2*>(&up.x));
            float2 f1 = __half22float2(*reinterpret_cast<__half2*>(&up.y));
            p0=f0.x; p1=f0.y; p2=f1.x; p3=f1.y;
            float z0 = p0+a0, z1 = p1+a1, z2 = p2+a2, z3 = p3+a3;
            s0 += z0; s1 += z1; s2 += z2; s3 += z3;
            q0 = fmaf(z0,z0,q0); q1 = fmaf(z1,z1,q1);
            q2 = fmaf(z2,z2,q2); q3 = fmaf(z3,z3,q3);
        }
        if (has2){
            float p0,p1,p2,p3, a0,a1,a2,a3;
            qt_sum4(uq2, ut2, a0,a1,a2,a3);
            float2 f0 = __half22float2(*reinterpret_cast<__half2*>(&up2.x));
            float2 f1 = __half22float2(*reinterpret_cast<__half2*>(&up2.y));
            p0=f0.x; p1=f0.y; p2=f1.x; p3=f1.y;
            float z0 = p0+a0, z1 = p1+a1, z2 = p2+a2, z3 = p3+a3;
            s0 += z0; s1 += z1; s2 += z2; s3 += z3;
            q0 = fmaf(z0,z0,q0); q1 = fmaf(z1,z1,q1);
            q2 = fmaf(z2,z2,q2); q3 = fmaf(z3,z3,q3);
        }
    }
    int c = lane*4;   // pos-space
    atomicAdd(&s_sum[c+0],s0); atomicAdd(&s_sum[c+1],s1); atomicAdd(&s_sum[c+2],s2); atomicAdd(&s_sum[c+3],s3);
    atomicAdd(&s_ssq[c+0],q0); atomicAdd(&s_ssq[c+1],q1); atomicAdd(&s_ssq[c+2],q2); atomicAdd(&s_ssq[c+3],q3);
    __syncthreads();
    if (threadIdx.x < 128){
        atomicAdd(&g_bn_sum[layer*128 + threadIdx.x], (double)s_sum[threadIdx.x]);
        atomicAdd(&g_bn_ssq[layer*128 + threadIdx.x], (double)s_ssq[threadIdx.x]);
    }
}

// ---- pass2 (warp per node): BN finalize inline, recompute z, act, agg, LN, residual ----
// inner loop unrolled x4: all 8 gathers for 4 edges issued before any compute
__global__ void edge_pass2(const float* __restrict__ lng, const float* __restrict__ lnb,
                           const float* __restrict__ bg,  const float* __restrict__ bb,
                           int layer, const int* __restrict__ batch, int do_pool){
    __shared__ __align__(16) float s_ss[256];    // scale[128] | shift[128] (pos-space)
    {
        int t = threadIdx.x;
        if (t < 128){
            int c = 2*(t >> 2) + (t & 1) + (((t >> 1) & 1) << 6);   // inverse perm
            double mu  = g_bn_sum[layer*128 + t] * (1.0/NSAMP);
            double var = g_bn_ssq[layer*128 + t] * (1.0/NSAMP) - mu*mu;
            double inv = 1.0 / sqrt(var + 1e-5);
            double sc  = (double)__ldg(bg + c) * inv;
            s_ss[t]       = (float)sc;
            s_ss[128 + t] = (float)((double)__ldg(bb + c) - mu*sc);
        }
    }
    __syncthreads();
    const __half* Tl = g_Th6 + (size_t)layer*MT2*128;
    int lane = threadIdx.x & 31;
    int warp = (blockIdx.x*blockDim.x + threadIdx.x) >> 5;
    int nw   = (gridDim.x*blockDim.x) >> 5;
    float4 sc = *reinterpret_cast<const float4*>(s_ss + lane*4);
    float4 sh = *reinterpret_cast<const float4*>(s_ss + 128 + lane*4);
    float2 lg = *reinterpret_cast<const float2*>(lng + 2*lane);
    float2 lb = *reinterpret_cast<const float2*>(lnb + 2*lane);
    for (int n = warp; n < NN; n += nw){
        int i0 = g_rowstart[n], i1 = g_rowstart[n+1];
        float p0,p1,p2,p3;
        ld_h4(g_Ph + n*128 + lane*4, p0,p1,p2,p3);
        float ph0 = fmaf(p0, sc.x, sh.x);
        float ph1 = fmaf(p1, sc.y, sh.y);
        float ph2 = fmaf(p2, sc.z, sh.z);
        float ph3 = fmaf(p3, sc.w, sh.w);
        float a0 = 0.0f, a1 = 0.0f;
        for (int base = i0; base < i1; base += 32){
            int cnt = min(32, i1 - base);
            unsigned myv = 0;
            if (base + lane < i1) myv = __ldg(&g_pack[base + lane]);
            int e = 0;
            for (; e + 4 <= cnt; e += 4){
                unsigned v[4];
                uint2 uq[4], ut[4];
                #pragma unroll
                for (int k = 0; k < 4; k++)
                    v[k] = __shfl_sync(0xffffffffu, myv, e + k);
                #pragma unroll
                for (int k = 0; k < 4; k++){
                    uq[k] = *reinterpret_cast<const uint2*>(g_Qh + (v[k] & 0x7FFFu)*128 + lane*4);
                    ut[k] = *reinterpret_cast<const uint2*>(Tl + (size_t)(v[k] >> 15)*128 + lane*4);
                }
                #pragma unroll
                for (int k = 0; k < 4; k++){
                    float A0,A1,A2,A3;
                    qt_sum4(uq[k], ut[k], A0,A1,A2,A3);
                    float z0 = fmaf(A0, sc.x, ph0);
                    float z1 = fmaf(A1, sc.y, ph1);
                    float z2 = fmaf(A2, sc.z, ph2);
                    float z3 = fmaf(A3, sc.w, ph3);
                    a0 = fmaf(sigmt(z0), splusf(z2), a0);
                    a1 = fmaf(sigmt(z1), splusf(z3), a1);
                }
            }
            for (; e < cnt; e++){
                unsigned va = __shfl_sync(0xffffffffu, myv, e);
                uint2 uq = *reinterpret_cast<const uint2*>(g_Qh + (va & 0x7FFFu)*128 + lane*4);
                uint2 ut = *reinterpret_cast<const uint2*>(Tl + (size_t)(va >> 15)*128 + lane*4);
                float A0,A1,A2,A3;
                qt_sum4(uq, ut, A0,A1,A2,A3);
                float z0 = fmaf(A0, sc.x, ph0);
                float z1 = fmaf(A1, sc.y, ph1);
                float z2 = fmaf(A2, sc.z, ph2);
                float z3 = fmaf(A3, sc.w, ph3);
                a0 = fmaf(sigmt(z0), splusf(z2), a0);
                a1 = fmaf(sigmt(z1), splusf(z3), a1);
            }
        }
        // LayerNorm over 64 channels (2 per lane: ch 2L, 2L+1)
        float s = a0 + a1;
        #pragma unroll
        for (int o = 16; o > 0; o >>= 1) s += __shfl_xor_sync(0xffffffffu, s, o);
        float mu = s * (1.0f/64.0f);
        float d0 = a0 - mu, d1 = a1 - mu;
        float vv = d0*d0 + d1*d1;
        #pragma unroll
        for (int o = 16; o > 0; o >>= 1) vv += __shfl_xor_sync(0xffffffffu, vv, o);
        float inv = rsqrtf(vv * (1.0f/64.0f) + 1e-5f);
        float2 x = *reinterpret_cast<const float2*>(g_x + n*64 + 2*lane);
        float h0 = fmaf(d0*inv, lg.x, lb.x) + x.x;
        float h1 = fmaf(d1*inv, lg.y, lb.y) + x.y;
        float xr0 = splusf(h0), xr1 = splusf(h1);
        if (do_pool){
            int g = __ldg(batch + n);
            atomicAdd(&g_mol[g*64 + 2*lane],     xr0);
            atomicAdd(&g_mol[g*64 + 2*lane + 1], xr1);
            if (lane == 0) atomicAdd(&g_cnt[g], 1.0f);
        } else {
            *reinterpret_cast<float2*>(g_x + n*64 + 2*lane) = make_float2(xr0, xr1);
        }
    }
}

// ---------------- fused MLP head ----------------
__global__ void mlp_all(const float* __restrict__ fc1W, const float* __restrict__ fc1b,
                        const float* __restrict__ fcsW, const float* __restrict__ fcsb,
                        const float* __restrict__ outW, const float* __restrict__ outb,
                        float* __restrict__ out){
    __shared__ float buf[2][FCW];
    __shared__ float red[FCW];
    int g = blockIdx.x, j = threadIdx.x;   // 128 threads
    if (j < 64){
        float c = fmaxf(g_cnt[g], 1.0f);
        buf[0][j] = g_mol[g*64 + j] / c;
    }
    __syncthreads();
    float acc = fc1b[j];
    #pragma unroll 4
    for (int f = 0; f < 64; f++) acc = fmaf(buf[0][f], __ldg(fc1W + f*FCW + j), acc);
    buf[1][j] = splusf(acc);
    __syncthreads();
    int cur = 1;
    for (int l = 0; l < 3; l++){
        const float* W = fcsW + l*FCW*FCW;
        float a = fcsb[l*FCW + j];
        #pragma unroll 4
        for (int f = 0; f < FCW; f++) a = fmaf(buf[cur][f], __ldg(W + f*FCW + j), a);
        buf[cur ^ 1][j] = splusf(a);
        cur ^= 1;
        __syncthreads();
    }
    red[j] = buf[cur][j] * __ldg(outW + j);
    __syncthreads();
    for (int o = 64; o > 0; o >>= 1){
        if (j < o) red[j] += red[j + o];
        __syncthreads();
    }
    if (j == 0) out[g] = red[0] + outb[0];
}

// ---------------- launch ----------------
extern "C" void kernel_launch(void* const* d_in, const int* in_sizes, int n_in,
                              void* d_out, int out_size){
    const int*   an    = (const int*)  d_in[0];
    const int*   nbr   = (const int*)  d_in[1];
    const float* dist  = (const float*)d_in[2];
    const int*   batch = (const int*)  d_in[3];
    const float* emb   = (const float*)d_in[4];
    const float* nucW  = (const float*)d_in[5];
    const float* nucb  = (const float*)d_in[6];
    const float* convW = (const float*)d_in[7];
    const float* convb = (const float*)d_in[8];
    const float* bng   = (const float*)d_in[9];
    const float* bnb   = (const float*)d_in[10];
    const float* lng   = (const float*)d_in[11];
    const float* lnb   = (const float*)d_in[12];
    const float* fc1W  = (const float*)d_in[13];
    const float* fc1b  = (const float*)d_in[14];
    const float* fcsW  = (const float*)d_in[15];
    const float* fcsb  = (const float*)d_in[16];
    const float* outW  = (const float*)d_in[17];
    const float* outb  = (const float*)d_in[18];
    float* y = (float*)d_out;

    cudaFuncSetAttribute(gemm_ab,      cudaFuncAttributeMaxDynamicSharedMemorySize, GEMM_SMEM);
    cudaFuncSetAttribute(build_tables, cudaFuncAttributeMaxDynamicSharedMemorySize, TAB_SMEM);

    // one-time: zero, all 6 tables, embedding, CSR build
    csr_zero<<<80, 256>>>();
    build_tables<<<NLAYER*TAB_BLOCKS, 256, TAB_SMEM>>>(convW, convb);
    nuc_kernel<<<640, 256>>>(an, emb, nucW, nucb);
    csr_hist<<<BIGGRID, 256>>>(nbr);
    csr_scan<<<1, 1024>>>();
    csr_scatter<<<BIGGRID, 256>>>(nbr, dist);

    for (int l = 0; l < NLAYER; l++){
        gemm_ab<<<625, 256, GEMM_SMEM>>>(convW + l*228*128);
        bn_pass<<<BIGGRID, 256>>>(nbr, dist, l);
        edge_pass2<<<BIGGRID, 256>>>(lng + l*64, lnb + l*64, bng + l*128, bnb + l*128,
                                     l, batch, l == NLAYER-1);
    }
    mlp_all<<<NGR, FCW>>>(fc1W, fc1b, fcsW, fcsb, outW, outb, y);
}

// round 12
// speedup vs baseline: 1.1576x; 1.1576x over previous
#include <cuda_runtime.h>
#include <cuda_fp16.h>
#include <math.h>

#define NN      20000
#define NNP     20480        // padded for csr_scan vector path
#define NE      500000
#define NGR     64
#define NGAUSS  100
#define NLAYER  6
#define FCW     128
#define EMBW    92

#define DELTA     (6.0f/99.0f)
#define INV_DELTA (99.0f/6.0f)
#define COEFF     (-0.5f/(DELTA*DELTA))

// nearest-neighbor distance table: h = DELTA/256
#define MT2       25346
#define T2_INVH   4224.0f    // 99*256/6
#define T2_H      (1.0f/4224.0f)

// BN statistics subsampling
#define SUB       8
#define NSAMP     (NE/SUB)   // 62500

#define TAB_BLOCKS 100       // blocks per layer for build_tables
#define GEMM_SMEM  ((64*256 + 32*64)*4)
#define TAB_SMEM   ((NGAUSS*128 + 128)*4)

// ---------------- scratch (device globals; no allocs allowed) ----------------
__device__ float  g_x[NN*64];
__device__ __half g_Ph[NN*128];           // P = x@W1, permuted, fp16
__device__ __half g_Qh[NN*128];           // Q = x@W2, permuted, fp16
__device__ __half g_Th6[NLAYER*MT2*128];  // all 6 layers' ef@W3+b tables, permuted fp16
__device__ int    g_deg[NNP];
__device__ int    g_rowstart[NNP+1];
__device__ int    g_cursor[NNP];
__device__ unsigned int g_pack[NE];       // src (15b) | m (<<15), CSR order
__device__ double g_bn_sum[NLAYER*128];
__device__ double g_bn_ssq[NLAYER*128];
__device__ float  g_mol[NGR*64];
__device__ float  g_cnt[NGR];

// ---------------- helpers ----------------
__device__ __forceinline__ float splusf(float x){
    float e = __expf(-fabsf(x));
    return fmaxf(x, 0.0f) + __logf(1.0f + e);
}
__device__ __forceinline__ float tanhx(float x){
    float y; asm("tanh.approx.f32 %0, %1;" : "=f"(y) : "f"(x)); return y;
}
__device__ __forceinline__ float sigmt(float x){   // sigmoid via 1 MUFU
    return fmaf(0.5f, tanhx(0.5f*x), 0.5f);
}
// channel c (0..127) -> permuted position: lane L holds {2L,2L+1,2L+64,2L+65}
__device__ __forceinline__ int chpos(int c){
    return ((c & 63) >> 1)*4 + ((c >> 6) << 1) + (c & 1);
}
__device__ __forceinline__ void ld_h4(const __half* p, float& a, float& b, float& c, float& d){
    uint2 u = *reinterpret_cast<const uint2*>(p);
    float2 f0 = __half22float2(*reinterpret_cast<__half2*>(&u.x));
    float2 f1 = __half22float2(*reinterpret_cast<__half2*>(&u.y));
    a = f0.x; b = f0.y; c = f1.x; d = f1.y;
}
// load q row + t row, add in half2, return 4 floats
__device__ __forceinline__ void qt_add4(const __half* q, const __half* t,
                                        float& a, float& b, float& c, float& d){
    uint2 uq = *reinterpret_cast<const uint2*>(q);
    uint2 ut = *reinterpret_cast<const uint2*>(t);
    __half2 s01 = __hadd2(*reinterpret_cast<__half2*>(&uq.x), *reinterpret_cast<__half2*>(&ut.x));
    __half2 s23 = __hadd2(*reinterpret_cast<__half2*>(&uq.y), *reinterpret_cast<__half2*>(&ut.y));
    float2 f0 = __half22float2(s01);
    float2 f1 = __half22float2(s23);
    a = f0.x; b = f0.y; c = f1.x; d = f1.y;
}

// ---------------- x = embedding[an] @ nuc_W + nuc_b ----------------
__global__ void nuc_kernel(const int* __restrict__ an, const float* __restrict__ emb,
                           const float* __restrict__ W, const float* __restrict__ b){
    __shared__ float Ws[EMBW*64];
    __shared__ float bs[64];
    for (int i = threadIdx.x; i < EMBW*64; i += blockDim.x) Ws[i] = W[i];
    if (threadIdx.x < 64) bs[threadIdx.x] = b[threadIdx.x];
    __syncthreads();
    int lane = threadIdx.x & 31;
    int warp = (blockIdx.x*blockDim.x + threadIdx.x) >> 5;
    int nw   = (gridDim.x*blockDim.x) >> 5;
    for (int n = warp; n < NN; n += nw){
        const float* er = emb + an[n]*EMBW;
        float a0 = bs[lane], a1 = bs[lane+32];
        #pragma unroll 4
        for (int e = 0; e < EMBW; e++){
            float v = __ldg(er + e);
            a0 = fmaf(v, Ws[e*64 + lane],      a0);
            a1 = fmaf(v, Ws[e*64 + lane + 32], a1);
        }
        g_x[n*64 + lane]      = a0;
        g_x[n*64 + lane + 32] = a1;
    }
}

// ---------------- one-time zeroing ----------------
__global__ void csr_zero(){
    int i = blockIdx.x*blockDim.x + threadIdx.x;
    if (i < NNP) g_deg[i] = 0;
    if (i < NGR*64) g_mol[i] = 0.0f;
    if (i < NGR)    g_cnt[i] = 0.0f;
    if (i < NLAYER*128){ g_bn_sum[i] = 0.0; g_bn_ssq[i] = 0.0; }
}
__global__ void csr_hist(const int* __restrict__ nbr){
    int i = blockIdx.x*blockDim.x + threadIdx.x;
    int stride = gridDim.x*blockDim.x;
    for (int e = i; e < NE; e += stride)
        atomicAdd(&g_deg[__ldg(nbr + NE + e)], 1);
}
__global__ void csr_scan(){   // single block, 1024 threads, 20 items each (padded)
    __shared__ int wsum[32];
    int t = threadIdx.x, lane = t & 31, wid = t >> 5;
    int base = t*20;
    int4 v[5];
    int loc = 0;
    #pragma unroll
    for (int j = 0; j < 5; j++){
        v[j] = *reinterpret_cast<const int4*>(g_deg + base + j*4);
        loc += v[j].x + v[j].y + v[j].z + v[j].w;
    }
    int sc = loc;
    #pragma unroll
    for (int off = 1; off < 32; off <<= 1){
        int u = __shfl_up_sync(0xffffffffu, sc, off);
        if (lane >= off) sc += u;
    }
    if (lane == 31) wsum[wid] = sc;
    __syncthreads();
    if (wid == 0){
        int w = wsum[lane];
        #pragma unroll
        for (int off = 1; off < 32; off <<= 1){
            int u = __shfl_up_sync(0xffffffffu, w, off);
            if (lane >= off) w += u;
        }
        wsum[lane] = w;
    }
    __syncthreads();
    int run = sc - loc + (wid ? wsum[wid-1] : 0);
    #pragma unroll
    for (int j = 0; j < 5; j++){
        int4 rs;
        rs.x = run; run += v[j].x;
        rs.y = run; run += v[j].y;
        rs.z = run; run += v[j].z;
        rs.w = run; run += v[j].w;
        *reinterpret_cast<int4*>(g_rowstart + base + j*4) = rs;
        *reinterpret_cast<int4*>(g_cursor   + base + j*4) = rs;
    }
    if (t == 1023) g_rowstart[NNP] = wsum[31];
}
__global__ void csr_scatter(const int* __restrict__ nbr, const float* __restrict__ dist){
    int i = blockIdx.x*blockDim.x + threadIdx.x;
    int stride = gridDim.x*blockDim.x;
    for (int e = i; e < NE; e += stride){
        int dn = __ldg(nbr + NE + e);
        int sn = __ldg(nbr + e);
        float d = __ldg(dist + e);
        int m = min(__float2int_rn(d * T2_INVH), MT2 - 1);
        int pos = atomicAdd(&g_cursor[dn], 1);
        g_pack[pos] = (unsigned)sn | ((unsigned)m << 15);
    }
}

// ---- build ALL 6 tables up front, warp-autonomous (no per-row barriers) ----
// T6[l][m] = ef(m*h)@W3_l + conv_b_l (fp16, permuted). Same FMA order as before.
__global__ void build_tables(const float* __restrict__ convW, const float* __restrict__ convb){
    extern __shared__ float sm[];
    float* W3s = sm;                 // [100][128]
    float* bs  = sm + NGAUSS*128;    // [128]
    int layer = blockIdx.x / TAB_BLOCKS;
    int tb    = blockIdx.x % TAB_BLOCKS;
    const float* W3 = convW + layer*228*128 + 128*128;
    const float* bl = convb + layer*128;
    __half* Tl = g_Th6 + (size_t)layer*MT2*128;
    for (int i = threadIdx.x; i < NGAUSS*128; i += blockDim.x) W3s[i] = W3[i];
    if (threadIdx.x < 128) bs[threadIdx.x] = bl[threadIdx.x];
    __syncthreads();
    int lane = threadIdx.x & 31;
    int wid  = threadIdx.x >> 5;     // 8 warps per block
    int c0 = lane*4;                 // this lane's 4 channels
    int p0 = chpos(c0), p1 = chpos(c0+1), p2 = chpos(c0+2), p3 = chpos(c0+3);
    float b0 = bs[c0], b1 = bs[c0+1], b2 = bs[c0+2], b3 = bs[c0+3];
    int per = (MT2 + TAB_BLOCKS - 1) / TAB_BLOCKS;    // 254
    int m0 = tb*per;
    int m1 = min(m0 + per, MT2);
    for (int m = m0 + wid; m < m1; m += 8){
        float d = (float)m * T2_H;
        int kc = __float2int_rn(d * INV_DELTA);
        int k0 = max(kc - 8, 0);
        int k1 = min(kc + 8, NGAUSS - 1);
        int cnt = k1 - k0 + 1;
        float myw = 0.0f;
        if (lane < cnt){ float t = d - (float)(k0+lane)*DELTA; myw = __expf(COEFF*t*t); }
        float a0 = b0, a1 = b1, a2 = b2, a3 = b3;
        for (int k = 0; k < cnt; k++){
            float w = __shfl_sync(0xffffffffu, myw, k);
            float4 wr = *reinterpret_cast<const float4*>(W3s + (k0+k)*128 + c0);
            a0 = fmaf(w, wr.x, a0);
            a1 = fmaf(w, wr.y, a1);
            a2 = fmaf(w, wr.z, a2);
            a3 = fmaf(w, wr.w, a3);
        }
        __half* out = Tl + (size_t)m*128;
        out[p0] = __float2half_rn(a0);
        out[p1] = __float2half_rn(a1);
        out[p2] = __float2half_rn(a2);
        out[p3] = __float2half_rn(a3);
    }
}

// ---------------- P = x@W1, Q = x@W2 (fp16, permuted) ----------------
__global__ void gemm_ab(const float* __restrict__ Wl){
    extern __shared__ float sm[];
    float* Wc = sm;             // [64][256]
    float* xt = sm + 64*256;    // [32][64]
    for (int i = threadIdx.x; i < 64*256; i += blockDim.x){
        int f = i >> 8, j = i & 255;
        Wc[i] = (j < 128) ? Wl[f*128 + j] : Wl[(64+f)*128 + (j-128)];
    }
    int n0 = blockIdx.x * 32;   // 625 * 32 == 20000
    for (int i = threadIdx.x; i < 32*64; i += blockDim.x)
        xt[i] = g_x[(n0 + (i>>6))*64 + (i&63)];
    __syncthreads();
    int j = threadIdx.x;
    float acc[32];
    #pragma unroll
    for (int t = 0; t < 32; t++) acc[t] = 0.0f;
    for (int f = 0; f < 64; f += 4){
        float w0 = Wc[f*256 + j], w1 = Wc[(f+1)*256 + j];
        float w2 = Wc[(f+2)*256 + j], w3 = Wc[(f+3)*256 + j];
        #pragma unroll
        for (int t = 0; t < 32; t++){
            float4 xv = *reinterpret_cast<const float4*>(xt + t*64 + f);
            acc[t] = fmaf(xv.x, w0, fmaf(xv.y, w1, fmaf(xv.z, w2, fmaf(xv.w, w3, acc[t]))));
        }
    }
    int cp = chpos(j & 127);
    if (j < 128){
        #pragma unroll
        for (int t = 0; t < 32; t++)
            g_Ph[(n0+t)*128 + cp] = __float2half_rn(acc[t]);
    } else {
        #pragma unroll
        for (int t = 0; t < 32; t++)
            g_Qh[(n0+t)*128 + cp] = __float2half_rn(acc[t]);
    }
}

// ---- BN stats over every SUB-th edge, edge-centric flat loop ----
__global__ void bn_pass(const int* __restrict__ nbr, const float* __restrict__ dist, int layer){
    __shared__ float s_sum[128];
    __shared__ float s_ssq[128];
    if (threadIdx.x < 128){ s_sum[threadIdx.x] = 0.0f; s_ssq[threadIdx.x] = 0.0f; }
    __syncthreads();
    const __half* Tl = g_Th6 + (size_t)layer*MT2*128;
    int lane = threadIdx.x & 31;
    int warp = (blockIdx.x*blockDim.x + threadIdx.x) >> 5;
    int nw   = (gridDim.x*blockDim.x) >> 5;
    float s0=0,s1=0,s2=0,s3=0, q0=0,q1=0,q2=0,q3=0;
    for (int s = warp; s < NSAMP; s += nw){
        int e = s * SUB;
        int dn = __ldg(nbr + NE + e);
        int sn = __ldg(nbr + e);
        float d = __ldg(dist + e);
        int m = min(__float2int_rn(d * T2_INVH), MT2 - 1);
        float p0,p1,p2,p3, a0,a1,a2,a3;
        ld_h4(g_Ph + dn*128 + lane*4, p0,p1,p2,p3);
        qt_add4(g_Qh + sn*128 + lane*4, Tl + (size_t)m*128 + lane*4, a0,a1,a2,a3);
        float z0 = p0+a0, z1 = p1+a1, z2 = p2+a2, z3 = p3+a3;
        s0 += z0; s1 += z1; s2 += z2; s3 += z3;
        q0 = fmaf(z0,z0,q0); q1 = fmaf(z1,z1,q1);
        q2 = fmaf(z2,z2,q2); q3 = fmaf(z3,z3,q3);
    }
    int c = lane*4;   // pos-space
    atomicAdd(&s_sum[c+0],s0); atomicAdd(&s_sum[c+1],s1); atomicAdd(&s_sum[c+2],s2); atomicAdd(&s_sum[c+3],s3);
    atomicAdd(&s_ssq[c+0],q0); atomicAdd(&s_ssq[c+1],q1); atomicAdd(&s_ssq[c+2],q2); atomicAdd(&s_ssq[c+3],q3);
    __syncthreads();
    if (threadIdx.x < 128){
        atomicAdd(&g_bn_sum[layer*128 + threadIdx.x], (double)s_sum[threadIdx.x]);
        atomicAdd(&g_bn_ssq[layer*128 + threadIdx.x], (double)s_ssq[threadIdx.x]);
    }
}

// ---- pass2 (warp per node): BN finalize inline, recompute z, act, agg, LN, residual ----
// last layer: fused mean-pool accumulate instead of g_x store
__global__ void edge_pass2(const float* __restrict__ lng, const float* __restrict__ lnb,
                           const float* __restrict__ bg,  const float* __restrict__ bb,
                           int layer, const int* __restrict__ batch, int do_pool){
    __shared__ __align__(16) float s_ss[256];    // scale[128] | shift[128] (pos-space)
    {
        int t = threadIdx.x;
        if (t < 128){
            int c = 2*(t >> 2) + (t & 1) + (((t >> 1) & 1) << 6);   // inverse perm
            double mu  = g_bn_sum[layer*128 + t] * (1.0/NSAMP);
            double var = g_bn_ssq[layer*128 + t] * (1.0/NSAMP) - mu*mu;
            double inv = 1.0 / sqrt(var + 1e-5);
            double sc  = (double)__ldg(bg + c) * inv;
            s_ss[t]       = (float)sc;
            s_ss[128 + t] = (float)((double)__ldg(bb + c) - mu*sc);
        }
    }
    __syncthreads();
    const __half* Tl = g_Th6 + (size_t)layer*MT2*128;
    int lane = threadIdx.x & 31;
    int warp = (blockIdx.x*blockDim.x + threadIdx.x) >> 5;
    int nw   = (gridDim.x*blockDim.x) >> 5;
    float4 sc = *reinterpret_cast<const float4*>(s_ss + lane*4);
    float4 sh = *reinterpret_cast<const float4*>(s_ss + 128 + lane*4);
    float2 lg = *reinterpret_cast<const float2*>(lng + 2*lane);
    float2 lb = *reinterpret_cast<const float2*>(lnb + 2*lane);
    for (int n = warp; n < NN; n += nw){
        int i0 = g_rowstart[n], i1 = g_rowstart[n+1];
        float p0,p1,p2,p3;
        ld_h4(g_Ph + n*128 + lane*4, p0,p1,p2,p3);
        // fold BN affine into per-node term: z = fmaf(q+t, sc, ph)
        float ph0 = fmaf(p0, sc.x, sh.x);
        float ph1 = fmaf(p1, sc.y, sh.y);
        float ph2 = fmaf(p2, sc.z, sh.z);
        float ph3 = fmaf(p3, sc.w, sh.w);
        float a0 = 0.0f, a1 = 0.0f;
        for (int base = i0; base < i1; base += 32){
            int cnt = min(32, i1 - base);
            unsigned myv = 0;
            if (base + lane < i1) myv = __ldg(&g_pack[base + lane]);
            int e = 0;
            for (; e + 2 <= cnt; e += 2){
                unsigned va = __shfl_sync(0xffffffffu, myv, e);
                unsigned vb = __shfl_sync(0xffffffffu, myv, e+1);
                float A0,A1,A2,A3, B0,B1,B2,B3;
                qt_add4(g_Qh + (va & 0x7FFFu)*128 + lane*4,
                        Tl + (size_t)(va >> 15)*128 + lane*4, A0,A1,A2,A3);
                qt_add4(g_Qh + (vb & 0x7FFFu)*128 + lane*4,
                        Tl + (size_t)(vb >> 15)*128 + lane*4, B0,B1,B2,B3);
                {
                    float z0 = fmaf(A0, sc.x, ph0);
                    float z1 = fmaf(A1, sc.y, ph1);
                    float z2 = fmaf(A2, sc.z, ph2);
                    float z3 = fmaf(A3, sc.w, ph3);
                    a0 = fmaf(sigmt(z0), splusf(z2), a0);
                    a1 = fmaf(sigmt(z1), splusf(z3), a1);
                }
                {
                    float z0 = fmaf(B0, sc.x, ph0);
                    float z1 = fmaf(B1, sc.y, ph1);
                    float z2 = fmaf(B2, sc.z, ph2);
                    float z3 = fmaf(B3, sc.w, ph3);
                    a0 = fmaf(sigmt(z0), splusf(z2), a0);
                    a1 = fmaf(sigmt(z1), splusf(z3), a1);
                }
            }
            if (e < cnt){
                unsigned va = __shfl_sync(0xffffffffu, myv, e);
                float A0,A1,A2,A3;
                qt_add4(g_Qh + (va & 0x7FFFu)*128 + lane*4,
                        Tl + (size_t)(va >> 15)*128 + lane*4, A0,A1,A2,A3);
                float z0 = fmaf(A0, sc.x, ph0);
                float z1 = fmaf(A1, sc.y, ph1);
                float z2 = fmaf(A2, sc.z, ph2);
                float z3 = fmaf(A3, sc.w, ph3);
                a0 = fmaf(sigmt(z0), splusf(z2), a0);
                a1 = fmaf(sigmt(z1), splusf(z3), a1);
            }
        }
        // LayerNorm over 64 channels (2 per lane: ch 2L, 2L+1)
        float s = a0 + a1;
        #pragma unroll
        for (int o = 16; o > 0; o >>= 1) s += __shfl_xor_sync(0xffffffffu, s, o);
        float mu = s * (1.0f/64.0f);
        float d0 = a0 - mu, d1 = a1 - mu;
        float vv = d0*d0 + d1*d1;
        #pragma unroll
        for (int o = 16; o > 0; o >>= 1) vv += __shfl_xor_sync(0xffffffffu, vv, o);
        float inv = rsqrtf(vv * (1.0f/64.0f) + 1e-5f);
        float2 x = *reinterpret_cast<const float2*>(g_x + n*64 + 2*lane);
        float h0 = fmaf(d0*inv, lg.x, lb.x) + x.x;
        float h1 = fmaf(d1*inv, lg.y, lb.y) + x.y;
        float xr0 = splusf(h0), xr1 = splusf(h1);
        if (do_pool){
            int g = __ldg(batch + n);
            atomicAdd(&g_mol[g*64 + 2*lane],     xr0);
            atomicAdd(&g_mol[g*64 + 2*lane + 1], xr1);
            if (lane == 0) atomicAdd(&g_cnt[g], 1.0f);
        } else {
            *reinterpret_cast<float2*>(g_x + n*64 + 2*lane) = make_float2(xr0, xr1);
        }
    }
}

// ---------------- fused MLP head ----------------
__global__ void mlp_all(const float* __restrict__ fc1W, const float* __restrict__ fc1b,
                        const float* __restrict__ fcsW, const float* __restrict__ fcsb,
                        const float* __restrict__ outW, const float* __restrict__ outb,
                        float* __restrict__ out){
    __shared__ float buf[2][FCW];
    __shared__ float red[FCW];
    int g = blockIdx.x, j = threadIdx.x;   // 128 threads
    if (j < 64){
        float c = fmaxf(g_cnt[g], 1.0f);
        buf[0][j] = g_mol[g*64 + j] / c;
    }
    __syncthreads();
    float acc = fc1b[j];
    #pragma unroll 4
    for (int f = 0; f < 64; f++) acc = fmaf(buf[0][f], __ldg(fc1W + f*FCW + j), acc);
    buf[1][j] = splusf(acc);
    __syncthreads();
    int cur = 1;
    for (int l = 0; l < 3; l++){
        const float* W = fcsW + l*FCW*FCW;
        float a = fcsb[l*FCW + j];
        #pragma unroll 4
        for (int f = 0; f < FCW; f++) a = fmaf(buf[cur][f], __ldg(W + f*FCW + j), a);
        buf[cur ^ 1][j] = splusf(a);
        cur ^= 1;
        __syncthreads();
    }
    red[j] = buf[cur][j] * __ldg(outW + j);
    __syncthreads();
    for (int o = 64; o > 0; o >>= 1){
        if (j < o) red[j] += red[j + o];
        __syncthreads();
    }
    if (j == 0) out[g] = red[0] + outb[0];
}

// ---------------- launch ----------------
extern "C" void kernel_launch(void* const* d_in, const int* in_sizes, int n_in,
                              void* d_out, int out_size){
    const int*   an    = (const int*)  d_in[0];
    const int*   nbr   = (const int*)  d_in[1];
    const float* dist  = (const float*)d_in[2];
    const int*   batch = (const int*)  d_in[3];
    const float* emb   = (const float*)d_in[4];
    const float* nucW  = (const float*)d_in[5];
    const float* nucb  = (const float*)d_in[6];
    const float* convW = (const float*)d_in[7];
    const float* convb = (const float*)d_in[8];
    const float* bng   = (const float*)d_in[9];
    const float* bnb   = (const float*)d_in[10];
    const float* lng   = (const float*)d_in[11];
    const float* lnb   = (const float*)d_in[12];
    const float* fc1W  = (const float*)d_in[13];
    const float* fc1b  = (const float*)d_in[14];
    const float* fcsW  = (const float*)d_in[15];
    const float* fcsb  = (const float*)d_in[16];
    const float* outW  = (const float*)d_in[17];
    const float* outb  = (const float*)d_in[18];
    float* y = (float*)d_out;

    // one-time resource creation (correctness call happens before graph capture)
    static cudaStream_t sA = 0, sB = 0;
    static cudaEvent_t  evR = 0, evA = 0, evB = 0;
    if (sA == 0){
        cudaStreamCreateWithFlags(&sA, cudaStreamNonBlocking);
        cudaStreamCreateWithFlags(&sB, cudaStreamNonBlocking);
        cudaEventCreateWithFlags(&evR, cudaEventDisableTiming);
        cudaEventCreateWithFlags(&evA, cudaEventDisableTiming);
        cudaEventCreateWithFlags(&evB, cudaEventDisableTiming);
    }

    cudaFuncSetAttribute(gemm_ab,      cudaFuncAttributeMaxDynamicSharedMemorySize, GEMM_SMEM);
    cudaFuncSetAttribute(build_tables, cudaFuncAttributeMaxDynamicSharedMemorySize, TAB_SMEM);

    // ---- forked setup: tables (sA) || nuc (sB) || csr chain (legacy) ----
    cudaEventRecord(evR, 0);
    cudaStreamWaitEvent(sA, evR, 0);
    cudaStreamWaitEvent(sB, evR, 0);

    build_tables<<<NLAYER*TAB_BLOCKS, 256, TAB_SMEM, sA>>>(convW, convb);
    nuc_kernel<<<640, 256, 0, sB>>>(an, emb, nucW, nucb);

    csr_zero<<<80, 256>>>();
    csr_hist<<<640, 256>>>(nbr);
    csr_scan<<<1, 1024>>>();
    csr_scatter<<<640, 256>>>(nbr, dist);

    cudaEventRecord(evA, sA);
    cudaEventRecord(evB, sB);
    cudaStreamWaitEvent(0, evA, 0);
    cudaStreamWaitEvent(0, evB, 0);

    // ---- per-layer pipeline (legacy stream, serial by dependency) ----
    for (int l = 0; l < NLAYER; l++){
        gemm_ab<<<625, 256, GEMM_SMEM>>>(convW + l*228*128);
        bn_pass<<<592, 256>>>(nbr, dist, l);
        edge_pass2<<<640, 256>>>(lng + l*64, lnb + l*64, bng + l*128, bnb + l*128,
                                 l, batch, l == NLAYER-1);
    }
    mlp_all<<<NGR, FCW>>>(fc1W, fc1b, fcsW, fcsb, outW, outb, y);
}

// round 13
// speedup vs baseline: 1.2408x; 1.0719x over previous
#include <cuda_runtime.h>
#include <cuda_fp16.h>
#include <cuda_bf16.h>
#include <math.h>

#define NN      20000
#define NNP     20480        // padded for csr_scan vector path
#define NE      500000
#define NGR     64
#define NGAUSS  100
#define NLAYER  6
#define FCW     128
#define EMBW    92

#define DELTA     (6.0f/99.0f)
#define INV_DELTA (99.0f/6.0f)
#define COEFF     (-0.5f/(DELTA*DELTA))

// nearest-neighbor distance table: h = DELTA/256
#define MT2       25346
#define T2_INVH   4224.0f    // 99*256/6
#define T2_H      (1.0f/4224.0f)

// BN statistics subsampling
#define SUB       8
#define NSAMP     (NE/SUB)   // 62500

#define TAB_BLOCKS 100       // blocks per layer for build_tables
#define TAB_SMEM   ((NGAUSS*128 + 128)*4)
#define GEMM_BLOCKS ((NN + 63)/64)   // 313

// smem strides (halves) padded for conflict-free ldmatrix
#define A_LD  72
#define B_LD  264

// ---------------- scratch (device globals; no allocs allowed) ----------------
__device__ float  g_x[NN*64];
__device__ __nv_bfloat16 g_xh[NN*64];     // bf16 copy of x for tensor-core gemm
__device__ __half g_Ph[NN*128];           // P = x@W1, permuted, fp16
__device__ __half g_Qh[NN*128];           // Q = x@W2, permuted, fp16
__device__ __half g_Th6[NLAYER*MT2*128];  // all 6 layers' ef@W3+b tables, permuted fp16
__device__ int    g_deg[NNP];
__device__ int    g_rowstart[NNP+1];
__device__ int    g_cursor[NNP];
__device__ unsigned int g_pack[NE];       // src (15b) | m (<<15), CSR order
__device__ double g_bn_sum[NLAYER*128];
__device__ double g_bn_ssq[NLAYER*128];
__device__ float  g_mol[NGR*64];
__device__ float  g_cnt[NGR];

// ---------------- helpers ----------------
__device__ __forceinline__ float splusf(float x){
    float e = __expf(-fabsf(x));
    return fmaxf(x, 0.0f) + __logf(1.0f + e);
}
__device__ __forceinline__ float tanhx(float x){
    float y; asm("tanh.approx.f32 %0, %1;" : "=f"(y) : "f"(x)); return y;
}
__device__ __forceinline__ float sigmt(float x){   // sigmoid via 1 MUFU
    return fmaf(0.5f, tanhx(0.5f*x), 0.5f);
}
// channel c (0..127) -> permuted position: lane L holds {2L,2L+1,2L+64,2L+65}
__device__ __forceinline__ int chpos(int c){
    return ((c & 63) >> 1)*4 + ((c >> 6) << 1) + (c & 1);
}
__device__ __forceinline__ void ld_h4(const __half* p, float& a, float& b, float& c, float& d){
    uint2 u = *reinterpret_cast<const uint2*>(p);
    float2 f0 = __half22float2(*reinterpret_cast<__half2*>(&u.x));
    float2 f1 = __half22float2(*reinterpret_cast<__half2*>(&u.y));
    a = f0.x; b = f0.y; c = f1.x; d = f1.y;
}
// load q row + t row, add in half2, return 4 floats
__device__ __forceinline__ void qt_add4(const __half* q, const __half* t,
                                        float& a, float& b, float& c, float& d){
    uint2 uq = *reinterpret_cast<const uint2*>(q);
    uint2 ut = *reinterpret_cast<const uint2*>(t);
    __half2 s01 = __hadd2(*reinterpret_cast<__half2*>(&uq.x), *reinterpret_cast<__half2*>(&ut.x));
    __half2 s23 = __hadd2(*reinterpret_cast<__half2*>(&uq.y), *reinterpret_cast<__half2*>(&ut.y));
    float2 f0 = __half22float2(s01);
    float2 f1 = __half22float2(s23);
    a = f0.x; b = f0.y; c = f1.x; d = f1.y;
}

// ---------------- x = embedding[an] @ nuc_W + nuc_b ----------------
__global__ void nuc_kernel(const int* __restrict__ an, const float* __restrict__ emb,
                           const float* __restrict__ W, const float* __restrict__ b){
    __shared__ float Ws[EMBW*64];
    __shared__ float bs[64];
    for (int i = threadIdx.x; i < EMBW*64; i += blockDim.x) Ws[i] = W[i];
    if (threadIdx.x < 64) bs[threadIdx.x] = b[threadIdx.x];
    __syncthreads();
    int lane = threadIdx.x & 31;
    int warp = (blockIdx.x*blockDim.x + threadIdx.x) >> 5;
    int nw   = (gridDim.x*blockDim.x) >> 5;
    for (int n = warp; n < NN; n += nw){
        const float* er = emb + an[n]*EMBW;
        float a0 = bs[lane], a1 = bs[lane+32];
        #pragma unroll 4
        for (int e = 0; e < EMBW; e++){
            float v = __ldg(er + e);
            a0 = fmaf(v, Ws[e*64 + lane],      a0);
            a1 = fmaf(v, Ws[e*64 + lane + 32], a1);
        }
        g_x[n*64 + lane]       = a0;
        g_x[n*64 + lane + 32]  = a1;
        g_xh[n*64 + lane]      = __float2bfloat16(a0);
        g_xh[n*64 + lane + 32] = __float2bfloat16(a1);
    }
}

// ---------------- one-time zeroing ----------------
__global__ void csr_zero(){
    int i = blockIdx.x*blockDim.x + threadIdx.x;
    if (i < NNP) g_deg[i] = 0;
    if (i < NGR*64) g_mol[i] = 0.0f;
    if (i < NGR)    g_cnt[i] = 0.0f;
    if (i < NLAYER*128){ g_bn_sum[i] = 0.0; g_bn_ssq[i] = 0.0; }
}
__global__ void csr_hist(const int* __restrict__ nbr){
    int i = blockIdx.x*blockDim.x + threadIdx.x;
    int stride = gridDim.x*blockDim.x;
    for (int e = i; e < NE; e += stride)
        atomicAdd(&g_deg[__ldg(nbr + NE + e)], 1);
}
__global__ void csr_scan(){   // single block, 1024 threads, 20 items each (padded)
    __shared__ int wsum[32];
    int t = threadIdx.x, lane = t & 31, wid = t >> 5;
    int base = t*20;
    int4 v[5];
    int loc = 0;
    #pragma unroll
    for (int j = 0; j < 5; j++){
        v[j] = *reinterpret_cast<const int4*>(g_deg + base + j*4);
        loc += v[j].x + v[j].y + v[j].z + v[j].w;
    }
    int sc = loc;
    #pragma unroll
    for (int off = 1; off < 32; off <<= 1){
        int u = __shfl_up_sync(0xffffffffu, sc, off);
        if (lane >= off) sc += u;
    }
    if (lane == 31) wsum[wid] = sc;
    __syncthreads();
    if (wid == 0){
        int w = wsum[lane];
        #pragma unroll
        for (int off = 1; off < 32; off <<= 1){
            int u = __shfl_up_sync(0xffffffffu, w, off);
            if (lane >= off) w += u;
        }
        wsum[lane] = w;
    }
    __syncthreads();
    int run = sc - loc + (wid ? wsum[wid-1] : 0);
    #pragma unroll
    for (int j = 0; j < 5; j++){
        int4 rs;
        rs.x = run; run += v[j].x;
        rs.y = run; run += v[j].y;
        rs.z = run; run += v[j].z;
        rs.w = run; run += v[j].w;
        *reinterpret_cast<int4*>(g_rowstart + base + j*4) = rs;
        *reinterpret_cast<int4*>(g_cursor   + base + j*4) = rs;
    }
    if (t == 1023) g_rowstart[NNP] = wsum[31];
}
__global__ void csr_scatter(const int* __restrict__ nbr, const float* __restrict__ dist){
    int i = blockIdx.x*blockDim.x + threadIdx.x;
    int stride = gridDim.x*blockDim.x;
    for (int e = i; e < NE; e += stride){
        int dn = __ldg(nbr + NE + e);
        int sn = __ldg(nbr + e);
        float d = __ldg(dist + e);
        int m = min(__float2int_rn(d * T2_INVH), MT2 - 1);
        int pos = atomicAdd(&g_cursor[dn], 1);
        g_pack[pos] = (unsigned)sn | ((unsigned)m << 15);
    }
}

// ---- build ALL 6 tables up front, warp-autonomous (no per-row barriers) ----
__global__ void build_tables(const float* __restrict__ convW, const float* __restrict__ convb){
    extern __shared__ float sm[];
    float* W3s = sm;                 // [100][128]
    float* bs  = sm + NGAUSS*128;    // [128]
    int layer = blockIdx.x / TAB_BLOCKS;
    int tb    = blockIdx.x % TAB_BLOCKS;
    const float* W3 = convW + layer*228*128 + 128*128;
    const float* bl = convb + layer*128;
    __half* Tl = g_Th6 + (size_t)layer*MT2*128;
    for (int i = threadIdx.x; i < NGAUSS*128; i += blockDim.x) W3s[i] = W3[i];
    if (threadIdx.x < 128) bs[threadIdx.x] = bl[threadIdx.x];
    __syncthreads();
    int lane = threadIdx.x & 31;
    int wid  = threadIdx.x >> 5;     // 8 warps per block
    int c0 = lane*4;                 // this lane's 4 channels
    int p0 = chpos(c0), p1 = chpos(c0+1), p2 = chpos(c0+2), p3 = chpos(c0+3);
    float b0 = bs[c0], b1 = bs[c0+1], b2 = bs[c0+2], b3 = bs[c0+3];
    int per = (MT2 + TAB_BLOCKS - 1) / TAB_BLOCKS;
    int m0 = tb*per;
    int m1 = min(m0 + per, MT2);
    for (int m = m0 + wid; m < m1; m += 8){
        float d = (float)m * T2_H;
        int kc = __float2int_rn(d * INV_DELTA);
        int k0 = max(kc - 8, 0);
        int k1 = min(kc + 8, NGAUSS - 1);
        int cnt = k1 - k0 + 1;
        float myw = 0.0f;
        if (lane < cnt){ float t = d - (float)(k0+lane)*DELTA; myw = __expf(COEFF*t*t); }
        float a0 = b0, a1 = b1, a2 = b2, a3 = b3;
        for (int k = 0; k < cnt; k++){
            float w = __shfl_sync(0xffffffffu, myw, k);
            float4 wr = *reinterpret_cast<const float4*>(W3s + (k0+k)*128 + c0);
            a0 = fmaf(w, wr.x, a0);
            a1 = fmaf(w, wr.y, a1);
            a2 = fmaf(w, wr.z, a2);
            a3 = fmaf(w, wr.w, a3);
        }
        __half* out = Tl + (size_t)m*128;
        out[p0] = __float2half_rn(a0);
        out[p1] = __float2half_rn(a1);
        out[p2] = __float2half_rn(a2);
        out[p3] = __float2half_rn(a3);
    }
}

// ---------------- P/Q gemm via tensor cores (mma.sync bf16, fp32 accum) --------
// D[64 nodes][256 cols] per block; cols 0..127 -> P, 128..255 -> Q (permuted fp16)
__global__ void gemm_mma(const float* __restrict__ Wl){
    __shared__ __nv_bfloat16 As[64*A_LD];
    __shared__ __nv_bfloat16 Bs[64*B_LD];
    int tid = threadIdx.x;
    int n0 = blockIdx.x * 64;
    // B[k][n]: n<128 -> W1[k][n] = Wl[k*128+n]; n>=128 -> W2[k][n-128] = Wl[(64+k)*128+(n-128)]
    for (int i = tid; i < 64*256; i += 256){
        int k = i >> 8, n = i & 255;
        float w = (n < 128) ? __ldg(Wl + k*128 + n) : __ldg(Wl + (64+k)*128 + (n-128));
        Bs[k*B_LD + n] = __float2bfloat16(w);
    }
    // A[r][k] = x_bf16[n0+r][k], zero-padded past NN
    for (int i = tid; i < 64*64; i += 256){
        int r = i >> 6, k = i & 63;
        int node = n0 + r;
        As[r*A_LD + k] = (node < NN) ? g_xh[node*64 + k] : __float2bfloat16(0.0f);
    }
    __syncthreads();
    int lane = tid & 31, wid = tid >> 5;
    int wm = (wid >> 2) * 32;     // node offset within block: 0 / 32
    int wn = (wid & 3) * 64;      // col offset: 0 / 64 / 128 / 192
    float acc[2][8][4];
    #pragma unroll
    for (int mt = 0; mt < 2; mt++)
        #pragma unroll
        for (int nt = 0; nt < 8; nt++)
            #pragma unroll
            for (int q = 0; q < 4; q++) acc[mt][nt][q] = 0.0f;

    int ar = lane & 15;            // A ldmatrix row
    int ac = (lane >> 4) * 8;      // A ldmatrix k-half
    int bk = lane & 7;             // B ldmatrix row-in-tile
    int bh = (lane >> 3) & 1;      // B tile half (k / k+8)
    #pragma unroll
    for (int ks = 0; ks < 4; ks++){
        unsigned a[2][4];
        #pragma unroll
        for (int mt = 0; mt < 2; mt++){
            unsigned sa = (unsigned)__cvta_generic_to_shared(
                As + (wm + mt*16 + ar)*A_LD + ks*16 + ac);
            asm volatile("ldmatrix.sync.aligned.m8n8.x4.shared.b16 {%0,%1,%2,%3}, [%4];"
                : "=r"(a[mt][0]), "=r"(a[mt][1]), "=r"(a[mt][2]), "=r"(a[mt][3]) : "r"(sa));
        }
        unsigned b[8][2];
        #pragma unroll
        for (int nt = 0; nt < 8; nt++){
            unsigned sb = (unsigned)__cvta_generic_to_shared(
                Bs + (ks*16 + bh*8 + bk)*B_LD + wn + nt*8);
            asm volatile("ldmatrix.sync.aligned.m8n8.x2.trans.shared.b16 {%0,%1}, [%2];"
                : "=r"(b[nt][0]), "=r"(b[nt][1]) : "r"(sb));
        }
        #pragma unroll
        for (int mt = 0; mt < 2; mt++)
            #pragma unroll
            for (int nt = 0; nt < 8; nt++){
                asm volatile(
                    "mma.sync.aligned.m16n8k16.row.col.f32.bf16.bf16.f32 "
                    "{%0,%1,%2,%3}, {%4,%5,%6,%7}, {%8,%9}, {%0,%1,%2,%3};"
                    : "+f"(acc[mt][nt][0]), "+f"(acc[mt][nt][1]),
                      "+f"(acc[mt][nt][2]), "+f"(acc[mt][nt][3])
                    : "r"(a[mt][0]), "r"(a[mt][1]), "r"(a[mt][2]), "r"(a[mt][3]),
                      "r"(b[nt][0]), "r"(b[nt][1]));
            }
    }
    // store to permuted fp16 P/Q
    #pragma unroll
    for (int mt = 0; mt < 2; mt++)
        #pragma unroll
        for (int nt = 0; nt < 8; nt++){
            int col = wn + nt*8 + (lane & 3)*2;
            __half* dst; int cp;
            if (col < 128){ dst = g_Ph; cp = chpos(col); }
            else          { dst = g_Qh; cp = chpos(col - 128); }
            int r0 = n0 + wm + mt*16 + (lane >> 2);
            if (r0 < NN){
                dst[r0*128 + cp]     = __float2half_rn(acc[mt][nt][0]);
                dst[r0*128 + cp + 1] = __float2half_rn(acc[mt][nt][1]);
            }
            int r1 = r0 + 8;
            if (r1 < NN){
                dst[r1*128 + cp]     = __float2half_rn(acc[mt][nt][2]);
                dst[r1*128 + cp + 1] = __float2half_rn(acc[mt][nt][3]);
            }
        }
}

// ---- BN stats over every SUB-th edge, edge-centric flat loop ----
__global__ void bn_pass(const int* __restrict__ nbr, const float* __restrict__ dist, int layer){
    __shared__ float s_sum[128];
    __shared__ float s_ssq[128];
    if (threadIdx.x < 128){ s_sum[threadIdx.x] = 0.0f; s_ssq[threadIdx.x] = 0.0f; }
    __syncthreads();
    const __half* Tl = g_Th6 + (size_t)layer*MT2*128;
    int lane = threadIdx.x & 31;
    int warp = (blockIdx.x*blockDim.x + threadIdx.x) >> 5;
    int nw   = (gridDim.x*blockDim.x) >> 5;
    float s0=0,s1=0,s2=0,s3=0, q0=0,q1=0,q2=0,q3=0;
    for (int s = warp; s < NSAMP; s += nw){
        int e = s * SUB;
        int dn = __ldg(nbr + NE + e);
        int sn = __ldg(nbr + e);
        float d = __ldg(dist + e);
        int m = min(__float2int_rn(d * T2_INVH), MT2 - 1);
        float p0,p1,p2,p3, a0,a1,a2,a3;
        ld_h4(g_Ph + dn*128 + lane*4, p0,p1,p2,p3);
        qt_add4(g_Qh + sn*128 + lane*4, Tl + (size_t)m*128 + lane*4, a0,a1,a2,a3);
        float z0 = p0+a0, z1 = p1+a1, z2 = p2+a2, z3 = p3+a3;
        s0 += z0; s1 += z1; s2 += z2; s3 += z3;
        q0 = fmaf(z0,z0,q0); q1 = fmaf(z1,z1,q1);
        q2 = fmaf(z2,z2,q2); q3 = fmaf(z3,z3,q3);
    }
    int c = lane*4;   // pos-space
    atomicAdd(&s_sum[c+0],s0); atomicAdd(&s_sum[c+1],s1); atomicAdd(&s_sum[c+2],s2); atomicAdd(&s_sum[c+3],s3);
    atomicAdd(&s_ssq[c+0],q0); atomicAdd(&s_ssq[c+1],q1); atomicAdd(&s_ssq[c+2],q2); atomicAdd(&s_ssq[c+3],q3);
    __syncthreads();
    if (threadIdx.x < 128){
        atomicAdd(&g_bn_sum[layer*128 + threadIdx.x], (double)s_sum[threadIdx.x]);
        atomicAdd(&g_bn_ssq[layer*128 + threadIdx.x], (double)s_ssq[threadIdx.x]);
    }
}

// ---- pass2 (warp per node): BN finalize inline, recompute z, act, agg, LN, residual ----
__global__ void edge_pass2(const float* __restrict__ lng, const float* __restrict__ lnb,
                           const float* __restrict__ bg,  const float* __restrict__ bb,
                           int layer, const int* __restrict__ batch, int do_pool){
    __shared__ __align__(16) float s_ss[256];    // scale[128] | shift[128] (pos-space)
    {
        int t = threadIdx.x;
        if (t < 128){
            int c = 2*(t >> 2) + (t & 1) + (((t >> 1) & 1) << 6);   // inverse perm
            double mu  = g_bn_sum[layer*128 + t] * (1.0/NSAMP);
            double var = g_bn_ssq[layer*128 + t] * (1.0/NSAMP) - mu*mu;
            double inv = 1.0 / sqrt(var + 1e-5);
            double sc  = (double)__ldg(bg + c) * inv;
            s_ss[t]       = (float)sc;
            s_ss[128 + t] = (float)((double)__ldg(bb + c) - mu*sc);
        }
    }
    __syncthreads();
    const __half* Tl = g_Th6 + (size_t)layer*MT2*128;
    int lane = threadIdx.x & 31;
    int warp = (blockIdx.x*blockDim.x + threadIdx.x) >> 5;
    int nw   = (gridDim.x*blockDim.x) >> 5;
    float4 sc = *reinterpret_cast<const float4*>(s_ss + lane*4);
    float4 sh = *reinterpret_cast<const float4*>(s_ss + 128 + lane*4);
    float2 lg = *reinterpret_cast<const float2*>(lng + 2*lane);
    float2 lb = *reinterpret_cast<const float2*>(lnb + 2*lane);
    for (int n = warp; n < NN; n += nw){
        int i0 = g_rowstart[n], i1 = g_rowstart[n+1];
        float p0,p1,p2,p3;
        ld_h4(g_Ph + n*128 + lane*4, p0,p1,p2,p3);
        float ph0 = fmaf(p0, sc.x, sh.x);
        float ph1 = fmaf(p1, sc.y, sh.y);
        float ph2 = fmaf(p2, sc.z, sh.z);
        float ph3 = fmaf(p3, sc.w, sh.w);
        float a0 = 0.0f, a1 = 0.0f;
        for (int base = i0; base < i1; base += 32){
            int cnt = min(32, i1 - base);
            unsigned myv = 0;
            if (base + lane < i1) myv = __ldg(&g_pack[base + lane]);
            int e = 0;
            for (; e + 2 <= cnt; e += 2){
                unsigned va = __shfl_sync(0xffffffffu, myv, e);
                unsigned vb = __shfl_sync(0xffffffffu, myv, e+1);
                float A0,A1,A2,A3, B0,B1,B2,B3;
                qt_add4(g_Qh + (va & 0x7FFFu)*128 + lane*4,
                        Tl + (size_t)(va >> 15)*128 + lane*4, A0,A1,A2,A3);
                qt_add4(g_Qh + (vb & 0x7FFFu)*128 + lane*4,
                        Tl + (size_t)(vb >> 15)*128 + lane*4, B0,B1,B2,B3);
                {
                    float z0 = fmaf(A0, sc.x, ph0);
                    float z1 = fmaf(A1, sc.y, ph1);
                    float z2 = fmaf(A2, sc.z, ph2);
                    float z3 = fmaf(A3, sc.w, ph3);
                    a0 = fmaf(sigmt(z0), splusf(z2), a0);
                    a1 = fmaf(sigmt(z1), splusf(z3), a1);
                }
                {
                    float z0 = fmaf(B0, sc.x, ph0);
                    float z1 = fmaf(B1, sc.y, ph1);
                    float z2 = fmaf(B2, sc.z, ph2);
                    float z3 = fmaf(B3, sc.w, ph3);
                    a0 = fmaf(sigmt(z0), splusf(z2), a0);
                    a1 = fmaf(sigmt(z1), splusf(z3), a1);
                }
            }
            if (e < cnt){
                unsigned va = __shfl_sync(0xffffffffu, myv, e);
                float A0,A1,A2,A3;
                qt_add4(g_Qh + (va & 0x7FFFu)*128 + lane*4,
                        Tl + (size_t)(va >> 15)*128 + lane*4, A0,A1,A2,A3);
                float z0 = fmaf(A0, sc.x, ph0);
                float z1 = fmaf(A1, sc.y, ph1);
                float z2 = fmaf(A2, sc.z, ph2);
                float z3 = fmaf(A3, sc.w, ph3);
                a0 = fmaf(sigmt(z0), splusf(z2), a0);
                a1 = fmaf(sigmt(z1), splusf(z3), a1);
            }
        }
        // LayerNorm over 64 channels (2 per lane: ch 2L, 2L+1)
        float s = a0 + a1;
        #pragma unroll
        for (int o = 16; o > 0; o >>= 1) s += __shfl_xor_sync(0xffffffffu, s, o);
        float mu = s * (1.0f/64.0f);
        float d0 = a0 - mu, d1 = a1 - mu;
        float vv = d0*d0 + d1*d1;
        #pragma unroll
        for (int o = 16; o > 0; o >>= 1) vv += __shfl_xor_sync(0xffffffffu, vv, o);
        float inv = rsqrtf(vv * (1.0f/64.0f) + 1e-5f);
        float2 x = *reinterpret_cast<const float2*>(g_x + n*64 + 2*lane);
        float h0 = fmaf(d0*inv, lg.x, lb.x) + x.x;
        float h1 = fmaf(d1*inv, lg.y, lb.y) + x.y;
        float xr0 = splusf(h0), xr1 = splusf(h1);
        if (do_pool){
            int g = __ldg(batch + n);
            atomicAdd(&g_mol[g*64 + 2*lane],     xr0);
            atomicAdd(&g_mol[g*64 + 2*lane + 1], xr1);
            if (lane == 0) atomicAdd(&g_cnt[g], 1.0f);
        } else {
            *reinterpret_cast<float2*>(g_x + n*64 + 2*lane) = make_float2(xr0, xr1);
            g_xh[n*64 + 2*lane]     = __float2bfloat16(xr0);
            g_xh[n*64 + 2*lane + 1] = __float2bfloat16(xr1);
        }
    }
}

// ---------------- fused MLP head ----------------
__global__ void mlp_all(const float* __restrict__ fc1W, const float* __restrict__ fc1b,
                        const float* __restrict__ fcsW, const float* __restrict__ fcsb,
                        const float* __restrict__ outW, const float* __restrict__ outb,
                        float* __restrict__ out){
    __shared__ float buf[2][FCW];
    __shared__ float red[FCW];
    int g = blockIdx.x, j = threadIdx.x;   // 128 threads
    if (j < 64){
        float c = fmaxf(g_cnt[g], 1.0f);
        buf[0][j] = g_mol[g*64 + j] / c;
    }
    __syncthreads();
    float acc = fc1b[j];
    #pragma unroll 4
    for (int f = 0; f < 64; f++) acc = fmaf(buf[0][f], __ldg(fc1W + f*FCW + j), acc);
    buf[1][j] = splusf(acc);
    __syncthreads();
    int cur = 1;
    for (int l = 0; l < 3; l++){
        const float* W = fcsW + l*FCW*FCW;
        float a = fcsb[l*FCW + j];
        #pragma unroll 4
        for (int f = 0; f < FCW; f++) a = fmaf(buf[cur][f], __ldg(W + f*FCW + j), a);
        buf[cur ^ 1][j] = splusf(a);
        cur ^= 1;
        __syncthreads();
    }
    red[j] = buf[cur][j] * __ldg(outW + j);
    __syncthreads();
    for (int o = 64; o > 0; o >>= 1){
        if (j < o) red[j] += red[j + o];
        __syncthreads();
    }
    if (j == 0) out[g] = red[0] + outb[0];
}

// ---------------- launch ----------------
extern "C" void kernel_launch(void* const* d_in, const int* in_sizes, int n_in,
                              void* d_out, int out_size){
    const int*   an    = (const int*)  d_in[0];
    const int*   nbr   = (const int*)  d_in[1];
    const float* dist  = (const float*)d_in[2];
    const int*   batch = (const int*)  d_in[3];
    const float* emb   = (const float*)d_in[4];
    const float* nucW  = (const float*)d_in[5];
    const float* nucb  = (const float*)d_in[6];
    const float* convW = (const float*)d_in[7];
    const float* convb = (const float*)d_in[8];
    const float* bng   = (const float*)d_in[9];
    const float* bnb   = (const float*)d_in[10];
    const float* lng   = (const float*)d_in[11];
    const float* lnb   = (const float*)d_in[12];
    const float* fc1W  = (const float*)d_in[13];
    const float* fc1b  = (const float*)d_in[14];
    const float* fcsW  = (const float*)d_in[15];
    const float* fcsb  = (const float*)d_in[16];
    const float* outW  = (const float*)d_in[17];
    const float* outb  = (const float*)d_in[18];
    float* y = (float*)d_out;

    // one-time resource creation (correctness call happens before graph capture)
    static cudaStream_t sA = 0, sB = 0;
    static cudaEvent_t  evR = 0, evA = 0, evB = 0;
    if (sA == 0){
        cudaStreamCreateWithFlags(&sA, cudaStreamNonBlocking);
        cudaStreamCreateWithFlags(&sB, cudaStreamNonBlocking);
        cudaEventCreateWithFlags(&evR, cudaEventDisableTiming);
        cudaEventCreateWithFlags(&evA, cudaEventDisableTiming);
        cudaEventCreateWithFlags(&evB, cudaEventDisableTiming);
    }

    cudaFuncSetAttribute(build_tables, cudaFuncAttributeMaxDynamicSharedMemorySize, TAB_SMEM);

    // ---- forked setup: tables (sA) || nuc (sB) || csr chain (legacy) ----
    cudaEventRecord(evR, 0);
    cudaStreamWaitEvent(sA, evR, 0);
    cudaStreamWaitEvent(sB, evR, 0);

    build_tables<<<NLAYER*TAB_BLOCKS, 256, TAB_SMEM, sA>>>(convW, convb);
    nuc_kernel<<<640, 256, 0, sB>>>(an, emb, nucW, nucb);

    csr_zero<<<80, 256>>>();
    csr_hist<<<640, 256>>>(nbr);
    csr_scan<<<1, 1024>>>();
    csr_scatter<<<640, 256>>>(nbr, dist);

    cudaEventRecord(evA, sA);
    cudaEventRecord(evB, sB);
    cudaStreamWaitEvent(0, evA, 0);
    cudaStreamWaitEvent(0, evB, 0);

    // ---- per-layer pipeline (legacy stream, serial by dependency) ----
    for (int l = 0; l < NLAYER; l++){
        gemm_mma<<<GEMM_BLOCKS, 256>>>(convW + l*228*128);
        bn_pass<<<592, 256>>>(nbr, dist, l);
        edge_pass2<<<640, 256>>>(lng + l*64, lnb + l*64, bng + l*128, bnb + l*128,
                                 l, batch, l == NLAYER-1);
    }
    mlp_all<<<NGR, FCW>>>(fc1W, fc1b, fcsW, fcsb, outW, outb, y);
}